// round 1
// baseline (speedup 1.0000x reference)
#include <cuda_runtime.h>
#include <math.h>

// Problem constants
#define B_  64
#define T_  512
#define D_  512
#define H_  1024
#define G4  4096   // 4*H

// Scratch (static device globals: allocation-free per harness rules)
__device__ float g_xw[(size_t)B_ * T_ * G4];   // [B*T, 4H] input projection, 512 MiB
__device__ float g_h[2][B_ * H_];              // ping-pong hidden state
__device__ float g_c[B_ * H_];                 // cell state (in-place)

// ---------------------------------------------------------------------------
// Init: zero h0 and c0 (must run every launch; graph replays from scratch)
// ---------------------------------------------------------------------------
__global__ void init_state_kernel() {
    int i = blockIdx.x * blockDim.x + threadIdx.x;
    if (i < B_ * H_) {
        g_h[0][i] = 0.0f;
        g_c[i] = 0.0f;
    }
}

// ---------------------------------------------------------------------------
// Phase 1: g_xw[m][n] = sum_k X[m][k] * W[k][n] + bias[n]
// M = B*T = 32768, K = D = 512, N = 4H = 4096
// Tile 64x64x32, 256 threads, 4x4 register blocking.
// ---------------------------------------------------------------------------
#define P1_BM 64
#define P1_BN 64
#define P1_BK 32

__global__ __launch_bounds__(256) void gemm_xw_kernel(
        const float* __restrict__ X, const float* __restrict__ W,
        const float* __restrict__ bias) {
    __shared__ float As[P1_BK][P1_BM + 1];             // [k][m], padded
    __shared__ __align__(16) float Bs[P1_BK][P1_BN];   // [k][n]

    const int tid = threadIdx.x;
    const int bm = blockIdx.y * P1_BM;
    const int bn = blockIdx.x * P1_BN;
    const int tm = tid >> 4;    // 0..15
    const int tn = tid & 15;    // 0..15

    float acc[4][4] = {};

    for (int k0 = 0; k0 < D_; k0 += P1_BK) {
        // Load A tile (64x32) transposed into smem: 512 float4 slots
        #pragma unroll
        for (int i = 0; i < 2; ++i) {
            int slot = tid + 256 * i;            // 0..511
            int m = slot >> 3;                   // 0..63
            int kk = (slot & 7) * 4;             // 0..28
            float4 v = *reinterpret_cast<const float4*>(
                &X[(size_t)(bm + m) * D_ + k0 + kk]);
            As[kk + 0][m] = v.x;
            As[kk + 1][m] = v.y;
            As[kk + 2][m] = v.z;
            As[kk + 3][m] = v.w;
        }
        // Load B tile (32x64): 512 float4 slots
        #pragma unroll
        for (int i = 0; i < 2; ++i) {
            int slot = tid + 256 * i;
            int k = slot >> 4;                   // 0..31
            int nn = (slot & 15) * 4;            // 0..60
            *reinterpret_cast<float4*>(&Bs[k][nn]) =
                *reinterpret_cast<const float4*>(&W[(size_t)(k0 + k) * G4 + bn + nn]);
        }
        __syncthreads();

        #pragma unroll
        for (int k = 0; k < P1_BK; ++k) {
            float4 bv = *reinterpret_cast<const float4*>(&Bs[k][tn * 4]);
            float a[4];
            #pragma unroll
            for (int r = 0; r < 4; ++r) a[r] = As[k][tm * 4 + r];
            #pragma unroll
            for (int r = 0; r < 4; ++r) {
                acc[r][0] = fmaf(a[r], bv.x, acc[r][0]);
                acc[r][1] = fmaf(a[r], bv.y, acc[r][1]);
                acc[r][2] = fmaf(a[r], bv.z, acc[r][2]);
                acc[r][3] = fmaf(a[r], bv.w, acc[r][3]);
            }
        }
        __syncthreads();
    }

    #pragma unroll
    for (int r = 0; r < 4; ++r) {
        #pragma unroll
        for (int c = 0; c < 4; ++c) {
            int n = bn + tn * 4 + c;
            g_xw[(size_t)(bm + tm * 4 + r) * G4 + n] = acc[r][c] + bias[n];
        }
    }
}

// ---------------------------------------------------------------------------
// Fused LSTM step: gates = xW[:,t,:] + h @ U ; pointwise update of c, h.
// Each CTA: 8 hidden units (=> 32 U columns across the 4 gates) x 64 batches.
// grid = 1024/8 = 128 CTAs, 128 threads, 4x4 register blocking, K=1024.
// ---------------------------------------------------------------------------
#define ST_NT 8
#define ST_NC 32      // 4 gates * ST_NT columns
#define ST_BK 32
#define ST_NKT (H_ / ST_BK)   // 32 K-tiles

__device__ __forceinline__ float sigmoidf_(float x) {
    return 1.0f / (1.0f + expf(-x));
}

__global__ __launch_bounds__(128) void lstm_step_kernel(
        int t, const float* __restrict__ U, float* __restrict__ final_out) {
    __shared__ float Hs[ST_BK][B_ + 1];                 // [k][b], padded
    __shared__ __align__(16) float Us[ST_BK][ST_NC];    // [k][cc]
    __shared__ float Gs[B_][ST_NC + 1];                 // gate pre-activations

    const int tid = threadIdx.x;
    const int n0 = blockIdx.x * ST_NT;
    const float* __restrict__ hin = g_h[t & 1];
    float* __restrict__ hout = g_h[(t + 1) & 1];

    const int tm = tid >> 3;   // 0..15 -> batch rows tm*4..+3
    const int tn = tid & 7;    // 0..7  -> cols   tn*4..+3

    float acc[4][4] = {};
    float4 hreg[4];
    float4 ureg[2];

    // Prologue: prefetch K-tile 0 into registers
    #pragma unroll
    for (int i = 0; i < 4; ++i) {
        int slot = tid + 128 * i;      // 0..511
        int b = slot >> 3;             // 0..63
        int kk4 = slot & 7;            // 0..7
        hreg[i] = *reinterpret_cast<const float4*>(&hin[b * H_ + kk4 * 4]);
    }
    #pragma unroll
    for (int i = 0; i < 2; ++i) {
        int slot = tid + 128 * i;      // 0..255
        int k = slot >> 3;             // 0..31
        int cc4 = slot & 7;            // 0..7
        int g = cc4 >> 1;              // gate 0..3
        int jb = g * H_ + n0 + (cc4 & 1) * 4;
        ureg[i] = *reinterpret_cast<const float4*>(&U[(size_t)k * G4 + jb]);
    }

    for (int kt = 0; kt < ST_NKT; ++kt) {
        // Commit prefetched tile to smem
        #pragma unroll
        for (int i = 0; i < 4; ++i) {
            int slot = tid + 128 * i;
            int b = slot >> 3;
            int kk = (slot & 7) * 4;
            Hs[kk + 0][b] = hreg[i].x;
            Hs[kk + 1][b] = hreg[i].y;
            Hs[kk + 2][b] = hreg[i].z;
            Hs[kk + 3][b] = hreg[i].w;
        }
        #pragma unroll
        for (int i = 0; i < 2; ++i) {
            int slot = tid + 128 * i;
            int k = slot >> 3;
            int cc4 = slot & 7;
            *reinterpret_cast<float4*>(&Us[k][cc4 * 4]) = ureg[i];
        }
        __syncthreads();

        // Prefetch next tile while computing this one
        if (kt + 1 < ST_NKT) {
            int k0 = (kt + 1) * ST_BK;
            #pragma unroll
            for (int i = 0; i < 4; ++i) {
                int slot = tid + 128 * i;
                int b = slot >> 3;
                int kk4 = slot & 7;
                hreg[i] = *reinterpret_cast<const float4*>(&hin[b * H_ + k0 + kk4 * 4]);
            }
            #pragma unroll
            for (int i = 0; i < 2; ++i) {
                int slot = tid + 128 * i;
                int k = slot >> 3;
                int cc4 = slot & 7;
                int g = cc4 >> 1;
                int jb = g * H_ + n0 + (cc4 & 1) * 4;
                ureg[i] = *reinterpret_cast<const float4*>(&U[(size_t)(k0 + k) * G4 + jb]);
            }
        }

        #pragma unroll
        for (int k = 0; k < ST_BK; ++k) {
            float4 uv = *reinterpret_cast<const float4*>(&Us[k][tn * 4]);
            float a[4];
            #pragma unroll
            for (int r = 0; r < 4; ++r) a[r] = Hs[k][tm * 4 + r];
            #pragma unroll
            for (int r = 0; r < 4; ++r) {
                acc[r][0] = fmaf(a[r], uv.x, acc[r][0]);
                acc[r][1] = fmaf(a[r], uv.y, acc[r][1]);
                acc[r][2] = fmaf(a[r], uv.z, acc[r][2]);
                acc[r][3] = fmaf(a[r], uv.w, acc[r][3]);
            }
        }
        __syncthreads();
    }

    // Stage gate pre-activations (add xW contribution) into smem
    #pragma unroll
    for (int r = 0; r < 4; ++r) {
        int b = tm * 4 + r;
        #pragma unroll
        for (int c = 0; c < 4; ++c) {
            int cc = tn * 4 + c;
            int g = cc >> 3;
            int o = cc & 7;
            float xw = g_xw[((size_t)b * T_ + t) * G4 + g * H_ + n0 + o];
            Gs[b][cc] = acc[r][c] + xw;
        }
    }
    __syncthreads();

    // Pointwise LSTM cell update: 512 (b, hid) pairs / 128 threads = 4 each
    const bool last = (t == T_ - 1);
    #pragma unroll
    for (int i = 0; i < 4; ++i) {
        int p = tid + 128 * i;     // 0..511
        int b = p >> 3;            // 0..63
        int o = p & 7;             // 0..7
        float gi = Gs[b][o];
        float gf = Gs[b][8 + o];
        float gc = Gs[b][16 + o];
        float go = Gs[b][24 + o];
        float iv = sigmoidf_(gi);
        float fv = sigmoidf_(gf);
        float cb = tanhf(gc);
        float ov = sigmoidf_(go);
        int idx = b * H_ + n0 + o;
        float cn = fv * g_c[idx] + iv * cb;
        g_c[idx] = cn;
        float hn = ov * tanhf(cn);
        hout[idx] = hn;
        if (last) final_out[idx] = hn;
    }
}

// ---------------------------------------------------------------------------
// Launch: init -> phase-1 GEMM -> 512 fused step kernels
// Inputs (metadata order): x [B,T,D] f32, W [D,4H] f32, U [H,4H] f32, b [4H] f32
// Output: h_T [B,H] f32
// ---------------------------------------------------------------------------
extern "C" void kernel_launch(void* const* d_in, const int* in_sizes, int n_in,
                              void* d_out, int out_size) {
    const float* x = (const float*)d_in[0];
    const float* W = (const float*)d_in[1];
    const float* U = (const float*)d_in[2];
    const float* b = (const float*)d_in[3];
    float* out = (float*)d_out;

    init_state_kernel<<<(B_ * H_ + 255) / 256, 256>>>();

    dim3 grid1(G4 / P1_BN, (B_ * T_) / P1_BM);   // (64, 512)
    gemm_xw_kernel<<<grid1, 256>>>(x, W, b);

    for (int t = 0; t < T_; ++t) {
        lstm_step_kernel<<<H_ / ST_NT, 128>>>(t, U, out);
    }
}

// round 3
// speedup vs baseline: 1.1791x; 1.1791x over previous
#include <cuda_runtime.h>
#include <math.h>

// Problem constants
#define B_  64
#define T_  512
#define D_  512
#define H_  1024
#define G4  4096   // 4*H

// Scratch (static device globals: allocation-free per harness rules)
__device__ float g_xw[(size_t)B_ * T_ * G4];   // [B*T, 4H] input projection
__device__ float g_h[2][B_ * H_];              // ping-pong hidden state
__device__ float g_c[B_ * H_];                 // cell state (in-place)

// ---------------------------------------------------------------------------
// Init: zero h0 and c0 (graph replays from scratch every time)
// ---------------------------------------------------------------------------
__global__ void init_state_kernel() {
    int i = blockIdx.x * blockDim.x + threadIdx.x;
    if (i < B_ * H_) {
        g_h[0][i] = 0.0f;
        g_c[i] = 0.0f;
    }
}

// ---------------------------------------------------------------------------
// Phase 1: g_xw[m][n] = sum_k X[m][k] * W[k][n] + bias[n]
// M = 32768, K = 512, N = 4096. Tile 64x64x32, 256 threads, 4x4 blocking.
// ---------------------------------------------------------------------------
#define P1_BM 64
#define P1_BN 64
#define P1_BK 32

__global__ __launch_bounds__(256) void gemm_xw_kernel(
        const float* __restrict__ X, const float* __restrict__ W,
        const float* __restrict__ bias) {
    __shared__ float As[P1_BK][P1_BM + 1];
    __shared__ __align__(16) float Bs[P1_BK][P1_BN];

    const int tid = threadIdx.x;
    const int bm = blockIdx.y * P1_BM;
    const int bn = blockIdx.x * P1_BN;
    const int tm = tid >> 4;
    const int tn = tid & 15;

    float acc[4][4] = {};

    for (int k0 = 0; k0 < D_; k0 += P1_BK) {
        #pragma unroll
        for (int i = 0; i < 2; ++i) {
            int slot = tid + 256 * i;
            int m = slot >> 3;
            int kk = (slot & 7) * 4;
            float4 v = *reinterpret_cast<const float4*>(
                &X[(size_t)(bm + m) * D_ + k0 + kk]);
            As[kk + 0][m] = v.x;
            As[kk + 1][m] = v.y;
            As[kk + 2][m] = v.z;
            As[kk + 3][m] = v.w;
        }
        #pragma unroll
        for (int i = 0; i < 2; ++i) {
            int slot = tid + 256 * i;
            int k = slot >> 4;
            int nn = (slot & 15) * 4;
            *reinterpret_cast<float4*>(&Bs[k][nn]) =
                *reinterpret_cast<const float4*>(&W[(size_t)(k0 + k) * G4 + bn + nn]);
        }
        __syncthreads();

        #pragma unroll
        for (int k = 0; k < P1_BK; ++k) {
            float4 bv = *reinterpret_cast<const float4*>(&Bs[k][tn * 4]);
            float a[4];
            #pragma unroll
            for (int r = 0; r < 4; ++r) a[r] = As[k][tm * 4 + r];
            #pragma unroll
            for (int r = 0; r < 4; ++r) {
                acc[r][0] = fmaf(a[r], bv.x, acc[r][0]);
                acc[r][1] = fmaf(a[r], bv.y, acc[r][1]);
                acc[r][2] = fmaf(a[r], bv.z, acc[r][2]);
                acc[r][3] = fmaf(a[r], bv.w, acc[r][3]);
            }
        }
        __syncthreads();
    }

    #pragma unroll
    for (int r = 0; r < 4; ++r) {
        #pragma unroll
        for (int c = 0; c < 4; ++c) {
            int n = bn + tn * 4 + c;
            g_xw[(size_t)(bm + tm * 4 + r) * G4 + n] = acc[r][c] + bias[n];
        }
    }
}

// ---------------------------------------------------------------------------
// Fused LSTM step, split-K version.
// CTA: 64 batches x 4 hidden units (16 gate-cols: col cc = gate*4 + offset).
// grid = 256 CTAs, 128 threads. Warps 0-1: K in [0,512); warps 2-3: [512,1024).
// Per K-partition: 64 threads, 4x4 register blocking, BK=16, 32 K-tiles.
// smem reduction across the two partitions, then fused pointwise update.
// ---------------------------------------------------------------------------
#define ST_NT 4            // hidden units per CTA
#define ST_NC 16           // 4 gates * ST_NT
#define ST_BK 16
#define ST_KZ 2            // split-K factor
#define ST_KP (H_ / ST_KZ)         // 512 K per partition
#define ST_NKT (ST_KP / ST_BK)     // 32 K-tiles per partition
#define HS_PAD 68          // row stride (words) for Hs: 16B-aligned, low conflicts

__device__ __forceinline__ float sigmoidf_(float x) {
    return 1.0f / (1.0f + expf(-x));
}

__global__ __launch_bounds__(128) void lstm_step_kernel(
        int t, const float* __restrict__ U, float* __restrict__ final_out) {
    __shared__ __align__(16) float Hs[ST_KZ][ST_BK][HS_PAD];  // [kz][k][b]
    __shared__ __align__(16) float Us[ST_KZ][ST_BK][ST_NC];   // [kz][k][cc]
    __shared__ float Gs[B_][ST_NC + 4];                       // reduce + gates

    const int tid = threadIdx.x;
    const int n0 = blockIdx.x * ST_NT;
    const float* __restrict__ hin = g_h[t & 1];
    float* __restrict__ hout = g_h[(t + 1) & 1];

    const int kz = tid >> 6;        // 0 or 1: K partition
    const int st = tid & 63;
    const int tm = st >> 2;         // 0..15 -> batch rows tm*4..+3
    const int tn = st & 3;          // 0..3  -> cols tn*4..+3

    float acc[4][4] = {};
    float4 hreg[4];
    float4 ureg;

    // Prologue: prefetch K-tile 0
    #pragma unroll
    for (int i = 0; i < 4; ++i) {
        int slot = tid + 128 * i;           // 0..511
        int kzp = slot >> 8;
        int rem = slot & 255;
        int b = rem >> 2;
        int kk4 = rem & 3;
        hreg[i] = *reinterpret_cast<const float4*>(
            &hin[b * H_ + kzp * ST_KP + kk4 * 4]);
    }
    {
        int kzp = tid >> 6;
        int rem = tid & 63;
        int k = rem >> 2;
        int g = rem & 3;
        ureg = *reinterpret_cast<const float4*>(
            &U[(size_t)(kzp * ST_KP + k) * G4 + g * H_ + n0]);
    }

    for (int kt = 0; kt < ST_NKT; ++kt) {
        // Commit prefetched tile to smem
        #pragma unroll
        for (int i = 0; i < 4; ++i) {
            int slot = tid + 128 * i;
            int kzp = slot >> 8;
            int rem = slot & 255;
            int b = rem >> 2;
            int kk = (rem & 3) * 4;
            Hs[kzp][kk + 0][b] = hreg[i].x;
            Hs[kzp][kk + 1][b] = hreg[i].y;
            Hs[kzp][kk + 2][b] = hreg[i].z;
            Hs[kzp][kk + 3][b] = hreg[i].w;
        }
        {
            int kzp = tid >> 6;
            int rem = tid & 63;
            int k = rem >> 2;
            int g = rem & 3;
            *reinterpret_cast<float4*>(&Us[kzp][k][g * 4]) = ureg;
        }
        __syncthreads();

        // Prefetch next tile while computing this one
        if (kt + 1 < ST_NKT) {
            int kb = (kt + 1) * ST_BK;
            #pragma unroll
            for (int i = 0; i < 4; ++i) {
                int slot = tid + 128 * i;
                int kzp = slot >> 8;
                int rem = slot & 255;
                int b = rem >> 2;
                int kk4 = rem & 3;
                hreg[i] = *reinterpret_cast<const float4*>(
                    &hin[b * H_ + kzp * ST_KP + kb + kk4 * 4]);
            }
            {
                int kzp = tid >> 6;
                int rem = tid & 63;
                int k = rem >> 2;
                int g = rem & 3;
                ureg = *reinterpret_cast<const float4*>(
                    &U[(size_t)(kzp * ST_KP + kb + k) * G4 + g * H_ + n0]);
            }
        }

        #pragma unroll
        for (int k = 0; k < ST_BK; ++k) {
            float4 uv = *reinterpret_cast<const float4*>(&Us[kz][k][tn * 4]);
            float4 av = *reinterpret_cast<const float4*>(&Hs[kz][k][tm * 4]);
            float a[4] = {av.x, av.y, av.z, av.w};
            #pragma unroll
            for (int r = 0; r < 4; ++r) {
                acc[r][0] = fmaf(a[r], uv.x, acc[r][0]);
                acc[r][1] = fmaf(a[r], uv.y, acc[r][1]);
                acc[r][2] = fmaf(a[r], uv.z, acc[r][2]);
                acc[r][3] = fmaf(a[r], uv.w, acc[r][3]);
            }
        }
        __syncthreads();
    }

    // Cross-partition reduction: kz=1 writes partials, kz=0 adds its own.
    if (kz == 1) {
        #pragma unroll
        for (int r = 0; r < 4; ++r)
            #pragma unroll
            for (int c = 0; c < 4; ++c)
                Gs[tm * 4 + r][tn * 4 + c] = acc[r][c];
    }
    __syncthreads();
    if (kz == 0) {
        #pragma unroll
        for (int r = 0; r < 4; ++r)
            #pragma unroll
            for (int c = 0; c < 4; ++c)
                Gs[tm * 4 + r][tn * 4 + c] += acc[r][c];
    }
    __syncthreads();

    // Pointwise LSTM update: 256 (b, o) pairs / 128 threads = 2 each.
    // Gate columns in Gs: cc = gate*4 + o.
    const bool last = (t == T_ - 1);
    #pragma unroll
    for (int i = 0; i < 2; ++i) {
        int p = tid + 128 * i;      // 0..255
        int b = p >> 2;             // 0..63
        int o = p & 3;              // 0..3
        const float* xwrow = &g_xw[((size_t)b * T_ + t) * G4 + n0 + o];
        float gi = Gs[b][0 + o]  + xwrow[0 * H_];
        float gf = Gs[b][4 + o]  + xwrow[1 * H_];
        float gc = Gs[b][8 + o]  + xwrow[2 * H_];
        float go = Gs[b][12 + o] + xwrow[3 * H_];
        float iv = sigmoidf_(gi);
        float fv = sigmoidf_(gf);
        float cb = tanhf(gc);
        float ov = sigmoidf_(go);
        int idx = b * H_ + n0 + o;
        float cn = fv * g_c[idx] + iv * cb;
        g_c[idx] = cn;
        float hn = ov * tanhf(cn);
        hout[idx] = hn;
        if (last) final_out[idx] = hn;
    }
}

// ---------------------------------------------------------------------------
// Launch: init -> phase-1 GEMM -> 512 fused step kernels
// ---------------------------------------------------------------------------
extern "C" void kernel_launch(void* const* d_in, const int* in_sizes, int n_in,
                              void* d_out, int out_size) {
    const float* x = (const float*)d_in[0];
    const float* W = (const float*)d_in[1];
    const float* U = (const float*)d_in[2];
    const float* b = (const float*)d_in[3];
    float* out = (float*)d_out;

    init_state_kernel<<<(B_ * H_ + 255) / 256, 256>>>();

    dim3 grid1(G4 / P1_BN, (B_ * T_) / P1_BM);   // (64, 512)
    gemm_xw_kernel<<<grid1, 256>>>(x, W, b);

    for (int t = 0; t < T_; ++t) {
        lstm_step_kernel<<<H_ / ST_NT, 128>>>(t, U, out);
    }
}

// round 5
// speedup vs baseline: 1.9356x; 1.6416x over previous
#include <cuda_runtime.h>
#include <cuda_bf16.h>
#include <math.h>
#include <stdint.h>

// Problem constants
#define B_  64
#define T_  512
#define D_  512
#define H_  1024
#define G4  4096   // 4*H

// ---------------------------------------------------------------------------
// Device globals (allocation-free scratch)
// ---------------------------------------------------------------------------
__device__ float g_xw[(size_t)B_ * T_ * G4];          // [B*T, 4H] input proj
__device__ __nv_bfloat16 g_uthi[(size_t)G4 * H_];     // U^T split hi: [4096][1024]
__device__ __nv_bfloat16 g_utlo[(size_t)G4 * H_];     // U^T split lo
__device__ __nv_bfloat16 g_hhi[B_ * H_];              // h split hi [64][1024]
__device__ __nv_bfloat16 g_hlo[B_ * H_];              // h split lo
__device__ float g_c[B_ * H_];                        // cell state
__device__ float g_part[2][64][B_ * 64];              // split-K partials
__device__ int   g_sem[64];                           // per-tile arrival sem

// ---------------------------------------------------------------------------
// PTX wrappers (inline functions, ptx_helpers.cuh style — no macros)
// ---------------------------------------------------------------------------
__device__ __forceinline__ void ldsm4(uint32_t& r0, uint32_t& r1,
                                      uint32_t& r2, uint32_t& r3,
                                      uint32_t addr) {
    asm volatile(
        "ldmatrix.sync.aligned.m8n8.x4.shared.b16 {%0,%1,%2,%3}, [%4];"
        : "=r"(r0), "=r"(r1), "=r"(r2), "=r"(r3)
        : "r"(addr));
}

__device__ __forceinline__ void mma_bf16(float* ac, const uint32_t* a,
                                         uint32_t b0, uint32_t b1) {
    asm volatile(
        "mma.sync.aligned.m16n8k16.row.col.f32.bf16.bf16.f32 "
        "{%0,%1,%2,%3}, {%4,%5,%6,%7}, {%8,%9}, {%0,%1,%2,%3};"
        : "+f"(ac[0]), "+f"(ac[1]), "+f"(ac[2]), "+f"(ac[3])
        : "r"(a[0]), "r"(a[1]), "r"(a[2]), "r"(a[3]), "r"(b0), "r"(b1));
}

__device__ __forceinline__ float sigmoidf_(float x) {
    return 1.0f / (1.0f + expf(-x));
}

// ---------------------------------------------------------------------------
// Init: zero h0 (both splits), c0, semaphores. Runs every launch.
// ---------------------------------------------------------------------------
__global__ void init_state_kernel() {
    int i = blockIdx.x * blockDim.x + threadIdx.x;
    if (i < B_ * H_) {
        g_hhi[i] = __float2bfloat16(0.0f);
        g_hlo[i] = __float2bfloat16(0.0f);
        g_c[i] = 0.0f;
    }
    if (i < 64) g_sem[i] = 0;
}

// ---------------------------------------------------------------------------
// Precompute: transpose U [K][4H] -> U^T [4H][K], split into bf16 hi + lo.
// ---------------------------------------------------------------------------
__global__ __launch_bounds__(256) void split_u_kernel(const float* __restrict__ U) {
    __shared__ float tile[32][33];
    const int k0 = blockIdx.x * 32;
    const int n0 = blockIdx.y * 32;
    const int tid = threadIdx.x;
    #pragma unroll
    for (int i = 0; i < 4; ++i) {
        int idx = tid + 256 * i;        // 0..1023
        int kl = idx >> 5, nl = idx & 31;
        tile[kl][nl] = U[(size_t)(k0 + kl) * G4 + n0 + nl];
    }
    __syncthreads();
    #pragma unroll
    for (int i = 0; i < 4; ++i) {
        int idx = tid + 256 * i;
        int nl = idx >> 5, kl = idx & 31;
        float v = tile[kl][nl];
        __nv_bfloat16 hi = __float2bfloat16(v);
        __nv_bfloat16 lo = __float2bfloat16(v - __bfloat162float(hi));
        size_t dst = (size_t)(n0 + nl) * H_ + k0 + kl;
        g_uthi[dst] = hi;
        g_utlo[dst] = lo;
    }
}

// ---------------------------------------------------------------------------
// Phase 1: g_xw = X @ W + bias   (fp32 SIMT GEMM, unchanged)
// ---------------------------------------------------------------------------
#define P1_BM 64
#define P1_BN 64
#define P1_BK 32

__global__ __launch_bounds__(256) void gemm_xw_kernel(
        const float* __restrict__ X, const float* __restrict__ W,
        const float* __restrict__ bias) {
    __shared__ float As[P1_BK][P1_BM + 1];
    __shared__ __align__(16) float Bs[P1_BK][P1_BN];

    const int tid = threadIdx.x;
    const int bm = blockIdx.y * P1_BM;
    const int bn = blockIdx.x * P1_BN;
    const int tm = tid >> 4;
    const int tn = tid & 15;

    float acc[4][4] = {};

    for (int k0 = 0; k0 < D_; k0 += P1_BK) {
        #pragma unroll
        for (int i = 0; i < 2; ++i) {
            int slot = tid + 256 * i;
            int m = slot >> 3;
            int kk = (slot & 7) * 4;
            float4 v = *reinterpret_cast<const float4*>(
                &X[(size_t)(bm + m) * D_ + k0 + kk]);
            As[kk + 0][m] = v.x;
            As[kk + 1][m] = v.y;
            As[kk + 2][m] = v.z;
            As[kk + 3][m] = v.w;
        }
        #pragma unroll
        for (int i = 0; i < 2; ++i) {
            int slot = tid + 256 * i;
            int k = slot >> 4;
            int nn = (slot & 15) * 4;
            *reinterpret_cast<float4*>(&Bs[k][nn]) =
                *reinterpret_cast<const float4*>(&W[(size_t)(k0 + k) * G4 + bn + nn]);
        }
        __syncthreads();
        #pragma unroll
        for (int k = 0; k < P1_BK; ++k) {
            float4 bv = *reinterpret_cast<const float4*>(&Bs[k][tn * 4]);
            float a[4];
            #pragma unroll
            for (int r = 0; r < 4; ++r) a[r] = As[k][tm * 4 + r];
            #pragma unroll
            for (int r = 0; r < 4; ++r) {
                acc[r][0] = fmaf(a[r], bv.x, acc[r][0]);
                acc[r][1] = fmaf(a[r], bv.y, acc[r][1]);
                acc[r][2] = fmaf(a[r], bv.z, acc[r][2]);
                acc[r][3] = fmaf(a[r], bv.w, acc[r][3]);
            }
        }
        __syncthreads();
    }

    #pragma unroll
    for (int r = 0; r < 4; ++r) {
        #pragma unroll
        for (int c = 0; c < 4; ++c) {
            int n = bn + tn * 4 + c;
            g_xw[(size_t)(bm + tm * 4 + r) * G4 + n] = acc[r][c] + bias[n];
        }
    }
}

// ---------------------------------------------------------------------------
// Fused LSTM step on tensor cores (mma.sync bf16, 2-term split = 3 mmas).
// Grid: 128 CTAs = 64 column-tiles (16 hidden units x 4 gates = 64 gate-cols)
//       x split-K 2 (kz). 256 threads = 8 warps (4 m-warps x 2 n-warps),
//       warp tile 16x32. A = h (resident smem), B = U^T tiles streamed.
// Split-K joined via g_part + semaphore; second-arriving CTA does reduction,
// xW add, pointwise, and writes next h as bf16 hi/lo.
// ---------------------------------------------------------------------------
#define A_STRIDE 520                  // bf16 elems per As row (512 + 8 pad)
#define B_STRIDE 40                   // bf16 elems per Bs row (32 + 8 pad)
#define OFF_AHI 0                     // 64*520*2 = 66560 B
#define OFF_ALO 66560
#define OFF_BHI 133120                // 64*40*2 = 5120 B
#define OFF_BLO 138240
#define OFF_GS  143360                // 64*66*4 = 16896 B
#define SMEM_BYTES 160256

__global__ __launch_bounds__(256, 1) void lstm_step_mma(
        int t, float* __restrict__ final_out) {
    extern __shared__ char smem[];
    __nv_bfloat16* Ahi = (__nv_bfloat16*)(smem + OFF_AHI);
    __nv_bfloat16* Alo = (__nv_bfloat16*)(smem + OFF_ALO);
    __nv_bfloat16* Bhi = (__nv_bfloat16*)(smem + OFF_BHI);
    __nv_bfloat16* Blo = (__nv_bfloat16*)(smem + OFF_BLO);
    float* Gsf = (float*)(smem + OFF_GS);
    __shared__ int s_old;

    const int tid = threadIdx.x;
    const int tile = blockIdx.x >> 1;        // 0..63 column tile
    const int kz = blockIdx.x & 1;           // K half
    const int n0 = tile * 16;                // hidden-unit base

    // ---- Load resident A (h hi/lo, this CTA's K half) into smem ----
    {
        const __nv_bfloat16* ghh = g_hhi + kz * 512;
        const __nv_bfloat16* ghl = g_hlo + kz * 512;
        #pragma unroll
        for (int i = 0; i < 16; ++i) {
            int slot = tid + 256 * i;        // 0..4095 (64 rows x 64 chunks)
            int row = slot >> 6;
            int j = slot & 63;               // 16B chunk (8 bf16)
            uint4 vh = *reinterpret_cast<const uint4*>(&ghh[row * H_ + j * 8]);
            uint4 vl = *reinterpret_cast<const uint4*>(&ghl[row * H_ + j * 8]);
            *reinterpret_cast<uint4*>(&Ahi[row * A_STRIDE + j * 8]) = vh;
            *reinterpret_cast<uint4*>(&Alo[row * A_STRIDE + j * 8]) = vl;
        }
    }

    // ---- B tile prefetch setup: thread -> (cc, 16B k-group) ----
    const int cc = tid >> 2;                 // 0..63 gate-col within tile
    const int kg = tid & 3;                  // 0..3
    const int colg = (cc >> 4) * H_ + n0 + (cc & 15);   // gate*1024 + n0 + off
    const __nv_bfloat16* ubh = g_uthi + (size_t)colg * H_ + kz * 512;
    const __nv_bfloat16* ubl = g_utlo + (size_t)colg * H_ + kz * 512;
    uint4 ph = *reinterpret_cast<const uint4*>(&ubh[kg * 8]);
    uint4 pl = *reinterpret_cast<const uint4*>(&ubl[kg * 8]);

    // ---- Warp / fragment addressing ----
    const int wid = tid >> 5, lane = tid & 31;
    const int m0 = (wid >> 1) * 16;          // warp M base
    const int nwb = (wid & 1) * 32;          // warp cc base
    const int gid = lane >> 2, tig = lane & 3;

    const int rowA = m0 + (lane & 15);
    const int kofsA = (lane >> 4) * 8;
    const uint32_t aAhi = (uint32_t)__cvta_generic_to_shared(Ahi)
                          + (uint32_t)(rowA * A_STRIDE + kofsA) * 2u;
    const uint32_t aAlo = (uint32_t)__cvta_generic_to_shared(Alo)
                          + (uint32_t)(rowA * A_STRIDE + kofsA) * 2u;

    const int rowBb = (lane & 7) + ((lane >> 4) << 3);
    const int kofsB = ((lane >> 3) & 1) * 8;
    const uint32_t aBhi0 = (uint32_t)__cvta_generic_to_shared(Bhi)
                           + (uint32_t)((nwb + rowBb) * B_STRIDE + kofsB) * 2u;
    const uint32_t aBhi1 = aBhi0 + 16u * B_STRIDE * 2u;
    const uint32_t aBlo0 = (uint32_t)__cvta_generic_to_shared(Blo)
                           + (uint32_t)((nwb + rowBb) * B_STRIDE + kofsB) * 2u;
    const uint32_t aBlo1 = aBlo0 + 16u * B_STRIDE * 2u;

    float acc[4][4] = {};

    // ---- Main loop: 16 B-tiles of BK=32 over this CTA's K half ----
    for (int kt = 0; kt < 16; ++kt) {
        *reinterpret_cast<uint4*>(&Bhi[cc * B_STRIDE + kg * 8]) = ph;
        *reinterpret_cast<uint4*>(&Blo[cc * B_STRIDE + kg * 8]) = pl;
        __syncthreads();
        if (kt + 1 < 16) {
            ph = *reinterpret_cast<const uint4*>(&ubh[(kt + 1) * 32 + kg * 8]);
            pl = *reinterpret_cast<const uint4*>(&ubl[(kt + 1) * 32 + kg * 8]);
        }
        #pragma unroll
        for (int ch = 0; ch < 2; ++ch) {
            const int kc = kt * 32 + ch * 16;     // col in As
            const int kcb = ch * 16;              // col in Bs
            uint32_t ah[4], al[4], bh0[4], bh1[4], bl0[4], bl1[4];
            ldsm4(ah[0], ah[1], ah[2], ah[3], aAhi + (uint32_t)kc * 2u);
            ldsm4(al[0], al[1], al[2], al[3], aAlo + (uint32_t)kc * 2u);
            ldsm4(bh0[0], bh0[1], bh0[2], bh0[3], aBhi0 + (uint32_t)kcb * 2u);
            ldsm4(bh1[0], bh1[1], bh1[2], bh1[3], aBhi1 + (uint32_t)kcb * 2u);
            ldsm4(bl0[0], bl0[1], bl0[2], bl0[3], aBlo0 + (uint32_t)kcb * 2u);
            ldsm4(bl1[0], bl1[1], bl1[2], bl1[3], aBlo1 + (uint32_t)kcb * 2u);
            // hi*hi
            mma_bf16(acc[0], ah, bh0[0], bh0[1]);
            mma_bf16(acc[1], ah, bh0[2], bh0[3]);
            mma_bf16(acc[2], ah, bh1[0], bh1[1]);
            mma_bf16(acc[3], ah, bh1[2], bh1[3]);
            // hi*lo
            mma_bf16(acc[0], ah, bl0[0], bl0[1]);
            mma_bf16(acc[1], ah, bl0[2], bl0[3]);
            mma_bf16(acc[2], ah, bl1[0], bl1[1]);
            mma_bf16(acc[3], ah, bl1[2], bl1[3]);
            // lo*hi
            mma_bf16(acc[0], al, bh0[0], bh0[1]);
            mma_bf16(acc[1], al, bh0[2], bh0[3]);
            mma_bf16(acc[2], al, bh1[0], bh1[1]);
            mma_bf16(acc[3], al, bh1[2], bh1[3]);
        }
        __syncthreads();
    }

    // ---- Write partials for this K half (frag layout -> row-major 64x64) ----
    float* mypart = &g_part[kz][tile][0];
    #pragma unroll
    for (int nf = 0; nf < 4; ++nf) {
        int col = nwb + nf * 8 + 2 * tig;
        *reinterpret_cast<float2*>(&mypart[(m0 + gid) * 64 + col]) =
            make_float2(acc[nf][0], acc[nf][1]);
        *reinterpret_cast<float2*>(&mypart[(m0 + gid + 8) * 64 + col]) =
            make_float2(acc[nf][2], acc[nf][3]);
    }
    __threadfence();
    __syncthreads();
    if (tid == 0) s_old = atomicAdd(&g_sem[tile], 1);
    __syncthreads();
    if (s_old != 2 * t + 1) return;          // first arriver done
    __threadfence();

    // ---- Second arriver: combine halves into Gs ----
    const float* opart = &g_part[kz ^ 1][tile][0];
    #pragma unroll
    for (int nf = 0; nf < 4; ++nf) {
        int col = nwb + nf * 8 + 2 * tig;
        float2 o0 = *reinterpret_cast<const float2*>(&opart[(m0 + gid) * 64 + col]);
        float2 o1 = *reinterpret_cast<const float2*>(&opart[(m0 + gid + 8) * 64 + col]);
        *reinterpret_cast<float2*>(&Gsf[(m0 + gid) * 66 + col]) =
            make_float2(acc[nf][0] + o0.x, acc[nf][1] + o0.y);
        *reinterpret_cast<float2*>(&Gsf[(m0 + gid + 8) * 66 + col]) =
            make_float2(acc[nf][2] + o1.x, acc[nf][3] + o1.y);
    }
    __syncthreads();

    // ---- Fused pointwise: 1024 (b, off) pairs / 256 threads = 4 each ----
    const bool last = (t == T_ - 1);
    #pragma unroll
    for (int i = 0; i < 4; ++i) {
        int p = tid + 256 * i;               // 0..1023
        int b = p >> 4;
        int off = p & 15;
        const float* xwrow = &g_xw[((size_t)b * T_ + t) * G4 + n0 + off];
        float gi = Gsf[b * 66 + 0 * 16 + off] + xwrow[0 * H_];
        float gf = Gsf[b * 66 + 1 * 16 + off] + xwrow[1 * H_];
        float gc = Gsf[b * 66 + 2 * 16 + off] + xwrow[2 * H_];
        float go = Gsf[b * 66 + 3 * 16 + off] + xwrow[3 * H_];
        float iv = sigmoidf_(gi);
        float fv = sigmoidf_(gf);
        float cb = tanhf(gc);
        float ov = sigmoidf_(go);
        int idx = b * H_ + n0 + off;
        float cn = fv * g_c[idx] + iv * cb;
        g_c[idx] = cn;
        float hn = ov * tanhf(cn);
        __nv_bfloat16 hh = __float2bfloat16(hn);
        g_hhi[idx] = hh;
        g_hlo[idx] = __float2bfloat16(hn - __bfloat162float(hh));
        if (last) final_out[idx] = hn;
    }
}

// ---------------------------------------------------------------------------
// Launch: init -> split U -> phase-1 GEMM -> 512 tensor-core step kernels
// ---------------------------------------------------------------------------
extern "C" void kernel_launch(void* const* d_in, const int* in_sizes, int n_in,
                              void* d_out, int out_size) {
    const float* x = (const float*)d_in[0];
    const float* W = (const float*)d_in[1];
    const float* U = (const float*)d_in[2];
    const float* b = (const float*)d_in[3];
    float* out = (float*)d_out;

    cudaFuncSetAttribute(lstm_step_mma,
                         cudaFuncAttributeMaxDynamicSharedMemorySize, SMEM_BYTES);

    init_state_kernel<<<(B_ * H_ + 255) / 256, 256>>>();

    dim3 gridu(H_ / 32, G4 / 32);            // (32, 128)
    split_u_kernel<<<gridu, 256>>>(U);

    dim3 grid1(G4 / P1_BN, (B_ * T_) / P1_BM);   // (64, 512)
    gemm_xw_kernel<<<grid1, 256>>>(x, W, b);

    for (int t = 0; t < T_; ++t) {
        lstm_step_mma<<<128, 256, SMEM_BYTES>>>(t, out);
    }
}

// round 12
// speedup vs baseline: 2.3451x; 1.2116x over previous
#include <cuda_runtime.h>
#include <cuda_bf16.h>
#include <math.h>
#include <stdint.h>

// Problem constants
#define B_  64
#define T_  512
#define D_  512
#define H_  1024
#define G4  4096   // 4*H

// ---------------------------------------------------------------------------
// Device globals (allocation-free scratch)
// ---------------------------------------------------------------------------
__device__ float g_xw[(size_t)B_ * T_ * G4];          // [B*T, 4H] input proj
__device__ __nv_bfloat16 g_uthi[(size_t)G4 * H_];     // U^T hi [4096][1024]
__device__ __nv_bfloat16 g_utlo[(size_t)G4 * H_];     // U^T lo
__device__ __nv_bfloat16 g_wthi[(size_t)G4 * D_];     // W^T hi [4096][512]
__device__ __nv_bfloat16 g_wtlo[(size_t)G4 * D_];     // W^T lo
__device__ __nv_bfloat16 g_xhi[(size_t)B_ * T_ * D_]; // x hi [32768][512]
__device__ __nv_bfloat16 g_xlo[(size_t)B_ * T_ * D_]; // x lo
__device__ __nv_bfloat16 g_hhi[B_ * H_];              // h split hi
__device__ __nv_bfloat16 g_hlo[B_ * H_];              // h split lo
__device__ float g_c[B_ * H_];                        // cell state
__device__ float g_part[2][64][B_ * 64];              // split-K partials
__device__ int   g_sem[64];                           // per-tile arrival sem

// ---------------------------------------------------------------------------
// PTX wrappers (round-5 proven)
// ---------------------------------------------------------------------------
__device__ __forceinline__ void ldsm4(uint32_t& r0, uint32_t& r1,
                                      uint32_t& r2, uint32_t& r3,
                                      uint32_t addr) {
    asm volatile(
        "ldmatrix.sync.aligned.m8n8.x4.shared.b16 {%0,%1,%2,%3}, [%4];"
        : "=r"(r0), "=r"(r1), "=r"(r2), "=r"(r3)
        : "r"(addr));
}

__device__ __forceinline__ void mma_bf16(float* ac, const uint32_t* a,
                                         uint32_t b0, uint32_t b1) {
    asm volatile(
        "mma.sync.aligned.m16n8k16.row.col.f32.bf16.bf16.f32 "
        "{%0,%1,%2,%3}, {%4,%5,%6,%7}, {%8,%9}, {%0,%1,%2,%3};"
        : "+f"(ac[0]), "+f"(ac[1]), "+f"(ac[2]), "+f"(ac[3])
        : "r"(a[0]), "r"(a[1]), "r"(a[2]), "r"(a[3]), "r"(b0), "r"(b1));
}

__device__ __forceinline__ float sigmoidf_(float x) {
    return 1.0f / (1.0f + expf(-x));
}

// ---------------------------------------------------------------------------
// Init: zero h0 (both splits), c0, semaphores. Runs every launch. (round-5)
// ---------------------------------------------------------------------------
__global__ void init_state_kernel() {
    int i = blockIdx.x * blockDim.x + threadIdx.x;
    if (i < B_ * H_) {
        g_hhi[i] = __float2bfloat16(0.0f);
        g_hlo[i] = __float2bfloat16(0.0f);
        g_c[i] = 0.0f;
    }
    if (i < 64) g_sem[i] = 0;
}

// ---------------------------------------------------------------------------
// Precompute: transpose U [K][4H] -> U^T [4H][K], bf16 hi/lo. (round-5 verbatim)
// ---------------------------------------------------------------------------
__global__ __launch_bounds__(256) void split_u_kernel(const float* __restrict__ U) {
    __shared__ float tile[32][33];
    const int k0 = blockIdx.x * 32;
    const int n0 = blockIdx.y * 32;
    const int tid = threadIdx.x;
    #pragma unroll
    for (int i = 0; i < 4; ++i) {
        int idx = tid + 256 * i;        // 0..1023
        int kl = idx >> 5, nl = idx & 31;
        tile[kl][nl] = U[(size_t)(k0 + kl) * G4 + n0 + nl];
    }
    __syncthreads();
    #pragma unroll
    for (int i = 0; i < 4; ++i) {
        int idx = tid + 256 * i;
        int nl = idx >> 5, kl = idx & 31;
        float v = tile[kl][nl];
        __nv_bfloat16 hi = __float2bfloat16(v);
        __nv_bfloat16 lo = __float2bfloat16(v - __bfloat162float(hi));
        size_t dst = (size_t)(n0 + nl) * H_ + k0 + kl;
        g_uthi[dst] = hi;
        g_utlo[dst] = lo;
    }
}

// ---------------------------------------------------------------------------
// Same pattern, hardcoded for W: [D][4H] -> W^T [4H][D], bf16 hi/lo.
// ---------------------------------------------------------------------------
__global__ __launch_bounds__(256) void split_w_kernel(const float* __restrict__ W) {
    __shared__ float tile[32][33];
    const int k0 = blockIdx.x * 32;
    const int n0 = blockIdx.y * 32;
    const int tid = threadIdx.x;
    #pragma unroll
    for (int i = 0; i < 4; ++i) {
        int idx = tid + 256 * i;
        int kl = idx >> 5, nl = idx & 31;
        tile[kl][nl] = W[(size_t)(k0 + kl) * G4 + n0 + nl];
    }
    __syncthreads();
    #pragma unroll
    for (int i = 0; i < 4; ++i) {
        int idx = tid + 256 * i;
        int nl = idx >> 5, kl = idx & 31;
        float v = tile[kl][nl];
        __nv_bfloat16 hi = __float2bfloat16(v);
        __nv_bfloat16 lo = __float2bfloat16(v - __bfloat162float(hi));
        size_t dst = (size_t)(n0 + nl) * D_ + k0 + kl;
        g_wthi[dst] = hi;
        g_wtlo[dst] = lo;
    }
}

// ---------------------------------------------------------------------------
// Elementwise bf16 hi/lo split of x
// ---------------------------------------------------------------------------
__global__ __launch_bounds__(256) void split_x_kernel(
        const float* __restrict__ x, int n) {
    int i = blockIdx.x * blockDim.x + threadIdx.x;
    if (i < n) {
        float v = x[i];
        __nv_bfloat16 hi = __float2bfloat16(v);
        g_xhi[i] = hi;
        g_xlo[i] = __float2bfloat16(v - __bfloat162float(hi));
    }
}

// ---------------------------------------------------------------------------
// Phase 1 on tensor cores, BM=64 x BN=64, DEFENSIVE register discipline:
// synchronous smem fill per BK=64 chunk, then three register-SCOPED passes
// (hi*hi, hi*lo, lo*hi), each pass = 3 ldsm4 + 8 mma in its own block so
// fragment registers are reused. Peak live regs ~70/thread.
// g_xw[m][n] = sum_k x[m][k]*W^T[n][k] + bias[n].
// ---------------------------------------------------------------------------
#define G1_STR 72      // smem row stride (64 + 8 pad), bf16 elems
__global__ __launch_bounds__(256) void gemm1_mma_kernel(
        const float* __restrict__ bias) {
    __shared__ __align__(16) __nv_bfloat16 Ahs[64][G1_STR];
    __shared__ __align__(16) __nv_bfloat16 Als[64][G1_STR];
    __shared__ __align__(16) __nv_bfloat16 Bhs[64][G1_STR];
    __shared__ __align__(16) __nv_bfloat16 Bls[64][G1_STR];

    const int tid = threadIdx.x;
    const int bn = blockIdx.x * 64;
    const int bm = blockIdx.y * 64;

    const __nv_bfloat16* xh = g_xhi + (size_t)bm * D_;
    const __nv_bfloat16* xl = g_xlo + (size_t)bm * D_;
    const __nv_bfloat16* wh = g_wthi + (size_t)bn * D_;
    const __nv_bfloat16* wl = g_wtlo + (size_t)bn * D_;

    // Warp / fragment addressing (round-5-proven layout)
    const int wid = tid >> 5, lane = tid & 31;
    const int m0 = (wid >> 1) * 16;          // warp M base
    const int nwb = (wid & 1) * 32;          // warp N base
    const int gid = lane >> 2, tig = lane & 3;

    const int rowA = m0 + (lane & 15);
    const int kofsA = (lane >> 4) * 8;
    const uint32_t aAh = (uint32_t)__cvta_generic_to_shared(&Ahs[0][0])
        + (uint32_t)(rowA * G1_STR + kofsA) * 2u;
    const uint32_t aAl = (uint32_t)__cvta_generic_to_shared(&Als[0][0])
        + (uint32_t)(rowA * G1_STR + kofsA) * 2u;

    const int rowBb = (lane & 7) + ((lane >> 4) << 3);
    const int kofsB = ((lane >> 3) & 1) * 8;
    const uint32_t aBh0 = (uint32_t)__cvta_generic_to_shared(&Bhs[0][0])
        + (uint32_t)((nwb + rowBb) * G1_STR + kofsB) * 2u;
    const uint32_t aBh1 = aBh0 + 16u * G1_STR * 2u;
    const uint32_t aBl0 = (uint32_t)__cvta_generic_to_shared(&Bls[0][0])
        + (uint32_t)((nwb + rowBb) * G1_STR + kofsB) * 2u;
    const uint32_t aBl1 = aBl0 + 16u * G1_STR * 2u;

    float acc[4][4] = {};

    for (int kc = 0; kc < 8; ++kc) {         // 8 chunks of BK=64
        const int k0 = kc * 64;
        // Synchronous global -> smem copy (transient registers only)
        #pragma unroll
        for (int i = 0; i < 2; ++i) {
            int slot = tid + 256 * i;        // 0..511
            int row = slot >> 3, j = slot & 7;
            *reinterpret_cast<uint4*>(&Ahs[row][j * 8]) =
                *reinterpret_cast<const uint4*>(&xh[(size_t)row * D_ + k0 + j * 8]);
            *reinterpret_cast<uint4*>(&Als[row][j * 8]) =
                *reinterpret_cast<const uint4*>(&xl[(size_t)row * D_ + k0 + j * 8]);
            *reinterpret_cast<uint4*>(&Bhs[row][j * 8]) =
                *reinterpret_cast<const uint4*>(&wh[(size_t)row * D_ + k0 + j * 8]);
            *reinterpret_cast<uint4*>(&Bls[row][j * 8]) =
                *reinterpret_cast<const uint4*>(&wl[(size_t)row * D_ + k0 + j * 8]);
        }
        __syncthreads();
        #pragma unroll
        for (int s = 0; s < 4; ++s) {        // 4 k16 per chunk
            const uint32_t kk = (uint32_t)(s * 16) * 2u;
            {   // pass 1: hi * hi
                uint32_t a[4], b0[4], b1[4];
                ldsm4(a[0], a[1], a[2], a[3], aAh + kk);
                ldsm4(b0[0], b0[1], b0[2], b0[3], aBh0 + kk);
                ldsm4(b1[0], b1[1], b1[2], b1[3], aBh1 + kk);
                mma_bf16(acc[0], a, b0[0], b0[1]);
                mma_bf16(acc[1], a, b0[2], b0[3]);
                mma_bf16(acc[2], a, b1[0], b1[1]);
                mma_bf16(acc[3], a, b1[2], b1[3]);
            }
            {   // pass 2: hi * lo
                uint32_t a[4], b0[4], b1[4];
                ldsm4(a[0], a[1], a[2], a[3], aAh + kk);
                ldsm4(b0[0], b0[1], b0[2], b0[3], aBl0 + kk);
                ldsm4(b1[0], b1[1], b1[2], b1[3], aBl1 + kk);
                mma_bf16(acc[0], a, b0[0], b0[1]);
                mma_bf16(acc[1], a, b0[2], b0[3]);
                mma_bf16(acc[2], a, b1[0], b1[1]);
                mma_bf16(acc[3], a, b1[2], b1[3]);
            }
            {   // pass 3: lo * hi
                uint32_t a[4], b0[4], b1[4];
                ldsm4(a[0], a[1], a[2], a[3], aAl + kk);
                ldsm4(b0[0], b0[1], b0[2], b0[3], aBh0 + kk);
                ldsm4(b1[0], b1[1], b1[2], b1[3], aBh1 + kk);
                mma_bf16(acc[0], a, b0[0], b0[1]);
                mma_bf16(acc[1], a, b0[2], b0[3]);
                mma_bf16(acc[2], a, b1[0], b1[1]);
                mma_bf16(acc[3], a, b1[2], b1[3]);
            }
        }
        __syncthreads();
    }

    // Epilogue: acc -> g_xw (+bias)
    #pragma unroll
    for (int nf = 0; nf < 4; ++nf) {
        int col = bn + nwb + nf * 8 + 2 * tig;
        float b0 = bias[col], b1 = bias[col + 1];
        size_t r0 = (size_t)(bm + m0 + gid) * G4 + col;
        size_t r1 = (size_t)(bm + m0 + gid + 8) * G4 + col;
        *reinterpret_cast<float2*>(&g_xw[r0]) =
            make_float2(acc[nf][0] + b0, acc[nf][1] + b1);
        *reinterpret_cast<float2*>(&g_xw[r1]) =
            make_float2(acc[nf][2] + b0, acc[nf][3] + b1);
    }
}

// ---------------------------------------------------------------------------
// Fused LSTM step (ROUND-5 VERBATIM — proven: 185 regs, no local, passed).
// 128 CTAs = 64 column-tiles x split-K 2; A = h resident smem; B = U^T
// streamed; split-K joined via g_part + semaphore; second arriver does
// reduction + xW + pointwise; writes next h as bf16 hi/lo.
// ---------------------------------------------------------------------------
#define A_STRIDE 520                  // bf16 elems per As row (512 + 8 pad)
#define B_STRIDE 40                   // bf16 elems per Bs row (32 + 8 pad)
#define OFF_AHI 0                     // 64*520*2 = 66560 B
#define OFF_ALO 66560
#define OFF_BHI 133120                // 64*40*2 = 5120 B
#define OFF_BLO 138240
#define OFF_GS  143360                // 64*66*4 = 16896 B
#define SMEM_BYTES 160256

__global__ __launch_bounds__(256, 1) void lstm_step_mma(
        int t, float* __restrict__ final_out) {
    extern __shared__ char smem[];
    __nv_bfloat16* Ahi = (__nv_bfloat16*)(smem + OFF_AHI);
    __nv_bfloat16* Alo = (__nv_bfloat16*)(smem + OFF_ALO);
    __nv_bfloat16* Bhi = (__nv_bfloat16*)(smem + OFF_BHI);
    __nv_bfloat16* Blo = (__nv_bfloat16*)(smem + OFF_BLO);
    float* Gsf = (float*)(smem + OFF_GS);
    __shared__ int s_old;

    const int tid = threadIdx.x;
    const int tile = blockIdx.x >> 1;        // 0..63 column tile
    const int kz = blockIdx.x & 1;           // K half
    const int n0 = tile * 16;                // hidden-unit base

    // ---- Load resident A (h hi/lo, this CTA's K half) into smem ----
    {
        const __nv_bfloat16* ghh = g_hhi + kz * 512;
        const __nv_bfloat16* ghl = g_hlo + kz * 512;
        #pragma unroll
        for (int i = 0; i < 16; ++i) {
            int slot = tid + 256 * i;        // 0..4095 (64 rows x 64 chunks)
            int row = slot >> 6;
            int j = slot & 63;               // 16B chunk (8 bf16)
            uint4 vh = *reinterpret_cast<const uint4*>(&ghh[row * H_ + j * 8]);
            uint4 vl = *reinterpret_cast<const uint4*>(&ghl[row * H_ + j * 8]);
            *reinterpret_cast<uint4*>(&Ahi[row * A_STRIDE + j * 8]) = vh;
            *reinterpret_cast<uint4*>(&Alo[row * A_STRIDE + j * 8]) = vl;
        }
    }

    // ---- B tile prefetch setup: thread -> (cc, 16B k-group) ----
    const int cc = tid >> 2;                 // 0..63 gate-col within tile
    const int kg = tid & 3;                  // 0..3
    const int colg = (cc >> 4) * H_ + n0 + (cc & 15);   // gate*1024 + n0 + off
    const __nv_bfloat16* ubh = g_uthi + (size_t)colg * H_ + kz * 512;
    const __nv_bfloat16* ubl = g_utlo + (size_t)colg * H_ + kz * 512;
    uint4 ph = *reinterpret_cast<const uint4*>(&ubh[kg * 8]);
    uint4 pl = *reinterpret_cast<const uint4*>(&ubl[kg * 8]);

    // ---- Warp / fragment addressing ----
    const int wid = tid >> 5, lane = tid & 31;
    const int m0 = (wid >> 1) * 16;          // warp M base
    const int nwb = (wid & 1) * 32;          // warp cc base
    const int gid = lane >> 2, tig = lane & 3;

    const int rowA = m0 + (lane & 15);
    const int kofsA = (lane >> 4) * 8;
    const uint32_t aAhi = (uint32_t)__cvta_generic_to_shared(Ahi)
                          + (uint32_t)(rowA * A_STRIDE + kofsA) * 2u;
    const uint32_t aAlo = (uint32_t)__cvta_generic_to_shared(Alo)
                          + (uint32_t)(rowA * A_STRIDE + kofsA) * 2u;

    const int rowBb = (lane & 7) + ((lane >> 4) << 3);
    const int kofsB = ((lane >> 3) & 1) * 8;
    const uint32_t aBhi0 = (uint32_t)__cvta_generic_to_shared(Bhi)
                           + (uint32_t)((nwb + rowBb) * B_STRIDE + kofsB) * 2u;
    const uint32_t aBhi1 = aBhi0 + 16u * B_STRIDE * 2u;
    const uint32_t aBlo0 = (uint32_t)__cvta_generic_to_shared(Blo)
                           + (uint32_t)((nwb + rowBb) * B_STRIDE + kofsB) * 2u;
    const uint32_t aBlo1 = aBlo0 + 16u * B_STRIDE * 2u;

    float acc[4][4] = {};

    // ---- Main loop: 16 B-tiles of BK=32 over this CTA's K half ----
    for (int kt = 0; kt < 16; ++kt) {
        *reinterpret_cast<uint4*>(&Bhi[cc * B_STRIDE + kg * 8]) = ph;
        *reinterpret_cast<uint4*>(&Blo[cc * B_STRIDE + kg * 8]) = pl;
        __syncthreads();
        if (kt + 1 < 16) {
            ph = *reinterpret_cast<const uint4*>(&ubh[(kt + 1) * 32 + kg * 8]);
            pl = *reinterpret_cast<const uint4*>(&ubl[(kt + 1) * 32 + kg * 8]);
        }
        #pragma unroll
        for (int ch = 0; ch < 2; ++ch) {
            const int kc = kt * 32 + ch * 16;     // col in As
            const int kcb = ch * 16;              // col in Bs
            uint32_t ah[4], al[4], bh0[4], bh1[4], bl0[4], bl1[4];
            ldsm4(ah[0], ah[1], ah[2], ah[3], aAhi + (uint32_t)kc * 2u);
            ldsm4(al[0], al[1], al[2], al[3], aAlo + (uint32_t)kc * 2u);
            ldsm4(bh0[0], bh0[1], bh0[2], bh0[3], aBhi0 + (uint32_t)kcb * 2u);
            ldsm4(bh1[0], bh1[1], bh1[2], bh1[3], aBhi1 + (uint32_t)kcb * 2u);
            ldsm4(bl0[0], bl0[1], bl0[2], bl0[3], aBlo0 + (uint32_t)kcb * 2u);
            ldsm4(bl1[0], bl1[1], bl1[2], bl1[3], aBlo1 + (uint32_t)kcb * 2u);
            // hi*hi
            mma_bf16(acc[0], ah, bh0[0], bh0[1]);
            mma_bf16(acc[1], ah, bh0[2], bh0[3]);
            mma_bf16(acc[2], ah, bh1[0], bh1[1]);
            mma_bf16(acc[3], ah, bh1[2], bh1[3]);
            // hi*lo
            mma_bf16(acc[0], ah, bl0[0], bl0[1]);
            mma_bf16(acc[1], ah, bl0[2], bl0[3]);
            mma_bf16(acc[2], ah, bl1[0], bl1[1]);
            mma_bf16(acc[3], ah, bl1[2], bl1[3]);
            // lo*hi
            mma_bf16(acc[0], al, bh0[0], bh0[1]);
            mma_bf16(acc[1], al, bh0[2], bh0[3]);
            mma_bf16(acc[2], al, bh1[0], bh1[1]);
            mma_bf16(acc[3], al, bh1[2], bh1[3]);
        }
        __syncthreads();
    }

    // ---- Write partials for this K half (frag layout -> row-major 64x64) ----
    float* mypart = &g_part[kz][tile][0];
    #pragma unroll
    for (int nf = 0; nf < 4; ++nf) {
        int col = nwb + nf * 8 + 2 * tig;
        *reinterpret_cast<float2*>(&mypart[(m0 + gid) * 64 + col]) =
            make_float2(acc[nf][0], acc[nf][1]);
        *reinterpret_cast<float2*>(&mypart[(m0 + gid + 8) * 64 + col]) =
            make_float2(acc[nf][2], acc[nf][3]);
    }
    __threadfence();
    __syncthreads();
    if (tid == 0) s_old = atomicAdd(&g_sem[tile], 1);
    __syncthreads();
    if (s_old != 2 * t + 1) return;          // first arriver done
    __threadfence();

    // ---- Second arriver: combine halves into Gs ----
    const float* opart = &g_part[kz ^ 1][tile][0];
    #pragma unroll
    for (int nf = 0; nf < 4; ++nf) {
        int col = nwb + nf * 8 + 2 * tig;
        float2 o0 = *reinterpret_cast<const float2*>(&opart[(m0 + gid) * 64 + col]);
        float2 o1 = *reinterpret_cast<const float2*>(&opart[(m0 + gid + 8) * 64 + col]);
        *reinterpret_cast<float2*>(&Gsf[(m0 + gid) * 66 + col]) =
            make_float2(acc[nf][0] + o0.x, acc[nf][1] + o0.y);
        *reinterpret_cast<float2*>(&Gsf[(m0 + gid + 8) * 66 + col]) =
            make_float2(acc[nf][2] + o1.x, acc[nf][3] + o1.y);
    }
    __syncthreads();

    // ---- Fused pointwise: 1024 (b, off) pairs / 256 threads = 4 each ----
    const bool last = (t == T_ - 1);
    #pragma unroll
    for (int i = 0; i < 4; ++i) {
        int p = tid + 256 * i;               // 0..1023
        int b = p >> 4;
        int off = p & 15;
        const float* xwrow = &g_xw[((size_t)b * T_ + t) * G4 + n0 + off];
        float gi = Gsf[b * 66 + 0 * 16 + off] + xwrow[0 * H_];
        float gf = Gsf[b * 66 + 1 * 16 + off] + xwrow[1 * H_];
        float gc = Gsf[b * 66 + 2 * 16 + off] + xwrow[2 * H_];
        float go = Gsf[b * 66 + 3 * 16 + off] + xwrow[3 * H_];
        float iv = sigmoidf_(gi);
        float fv = sigmoidf_(gf);
        float cb = tanhf(gc);
        float ov = sigmoidf_(go);
        int idx = b * H_ + n0 + off;
        float cn = fv * g_c[idx] + iv * cb;
        g_c[idx] = cn;
        float hn = ov * tanhf(cn);
        __nv_bfloat16 hh = __float2bfloat16(hn);
        g_hhi[idx] = hh;
        g_hlo[idx] = __float2bfloat16(hn - __bfloat162float(hh));
        if (last) final_out[idx] = hn;
    }
}

// ---------------------------------------------------------------------------
// Launch: init -> splits -> tensor-core phase-1 -> 512 round-5 step kernels
// ---------------------------------------------------------------------------
extern "C" void kernel_launch(void* const* d_in, const int* in_sizes, int n_in,
                              void* d_out, int out_size) {
    const float* x = (const float*)d_in[0];
    const float* W = (const float*)d_in[1];
    const float* U = (const float*)d_in[2];
    const float* b = (const float*)d_in[3];
    float* out = (float*)d_out;

    cudaFuncSetAttribute(lstm_step_mma,
                         cudaFuncAttributeMaxDynamicSharedMemorySize, SMEM_BYTES);

    init_state_kernel<<<(B_ * H_ + 255) / 256, 256>>>();

    dim3 gu(H_ / 32, G4 / 32);               // (32, 128)
    split_u_kernel<<<gu, 256>>>(U);
    dim3 gw(D_ / 32, G4 / 32);               // (16, 128)
    split_w_kernel<<<gw, 256>>>(W);

    int nx = B_ * T_ * D_;
    split_x_kernel<<<(nx + 255) / 256, 256>>>(x, nx);

    dim3 g1(G4 / 64, (B_ * T_) / 64);        // (64, 512)
    gemm1_mma_kernel<<<g1, 256>>>(b);

    for (int t = 0; t < T_; ++t) {
        lstm_step_mma<<<128, 256, SMEM_BYTES>>>(t, out);
    }
}